// round 4
// baseline (speedup 1.0000x reference)
#include <cuda_runtime.h>
#include <math.h>
#include <stdint.h>

typedef unsigned long long ull;

#define KA 12
#define HSZ 4608
#define INP 5024
#define EPSB 1e-5f

// big gemm tiling
#define CSZ 628
#define NCH 8
#define NRB 108     // 13824/128 rows (i,g,o gates only)
// head gemm tiling
#define CSZ2 768
#define NCH2 6
#define HROWS 320   // 128 (ah) + 192 (inf)

// scratch (device globals; no allocation allowed)
__device__ __align__(16) float g_h1[KA*16*576];
__device__ __align__(16) float g_h2[KA*16*576];
__device__ __align__(16) float g_h3[KA*8*576];
__device__ float g_sc1[16], g_sh1[16], g_sc2[16], g_sh2[16], g_sc3[8], g_sh3[8];
__device__ float g_op[192], g_om[192], g_mm[192];
__device__ __align__(16) float g_lsp[6*INP*2];     // agent-pair planes of lstm_in
__device__ __align__(16) float g_part[(size_t)NCH*13824*KA];
__device__ __align__(16) float g_hp[6*HSZ*2];      // agent-pair planes of relu(h)
__device__ __align__(16) float g_part2[(size_t)NCH2*HROWS*KA];
__device__ __align__(16) float g_t[KA*128];

__device__ __forceinline__ ull dup2(float a){ ull r; asm("mov.b64 %0,{%1,%1};":"=l"(r):"f"(a)); return r; }
__device__ __forceinline__ ull fma2(ull a, ull b, ull c){ ull d; asm("fma.rn.f32x2 %0,%1,%2,%3;":"=l"(d):"l"(a),"l"(b),"l"(c)); return d; }
__device__ __forceinline__ ull add2(ull a, ull b){ ull d; asm("add.rn.f32x2 %0,%1,%2;":"=l"(d):"l"(a),"l"(b)); return d; }

// ---------- conv1: 1x1 over (c,d) contraction ----------
__global__ __launch_bounds__(96) void k_conv1(const float* __restrict__ x,
                                              const float* __restrict__ w1,
                                              const float* __restrict__ b1){
    __shared__ float ws[16*256];
    int b = blockIdx.x, t6 = blockIdx.y, tid = threadIdx.x;
    for (int i = tid; i < 4096; i += 96) ws[i] = w1[i];
    __syncthreads();
    int px = t6*96 + tid;
    float acc[16];
#pragma unroll
    for (int o = 0; o < 16; o++) acc[o] = b1[o];
    const float* xb = x + (size_t)b*256*576 + px;
#pragma unroll 4
    for (int cd = 0; cd < 256; cd++){
        float xv = xb[(size_t)cd*576];
#pragma unroll
        for (int o = 0; o < 16; o++) acc[o] += xv * ws[o*256+cd];
    }
#pragma unroll
    for (int o = 0; o < 16; o++) g_h1[((size_t)b*16+o)*576 + px] = acc[o];
}

// ---------- BN stats (training-mode, biased var) ----------
__global__ void k_stats(int stage, const float* __restrict__ gamma,
                        const float* __restrict__ beta){
    const float* pre = (stage==0)? g_h1 : (stage==1)? g_h2 : g_h3;
    int C = (stage==2)? 8 : 16;
    float* sc = (stage==0)? g_sc1 : (stage==1)? g_sc2 : g_sc3;
    float* sh = (stage==0)? g_sh1 : (stage==1)? g_sh2 : g_sh3;
    int ch = blockIdx.x, tid = threadIdx.x;
    float s = 0.f, q = 0.f;
    for (int i = tid; i < KA*576; i += 256){
        int b = i/576, px = i%576;
        float v = pre[((size_t)b*C + ch)*576 + px];
        s += v; q += v*v;
    }
    __shared__ float ss[8], qq[8];
    for (int off = 16; off; off >>= 1){
        s += __shfl_xor_sync(0xffffffffu, s, off);
        q += __shfl_xor_sync(0xffffffffu, q, off);
    }
    if ((tid&31)==0){ ss[tid>>5]=s; qq[tid>>5]=q; }
    __syncthreads();
    if (tid==0){
        float S=0.f, Q=0.f;
        for (int w = 0; w < 8; w++){ S+=ss[w]; Q+=qq[w]; }
        float mu = S/6912.f, var = Q/6912.f - mu*mu;
        float r = rsqrtf(var + EPSB) * gamma[ch];
        sc[ch] = r; sh[ch] = beta[ch] - mu*r;
    }
}

// ---------- conv2: bn1+relu on load, 3x3 SAME ----------
__global__ __launch_bounds__(144) void k_conv2(const float* __restrict__ w2,
                                               const float* __restrict__ b2){
    __shared__ float in_s[16][8][24];
    __shared__ float ws[16*16*9];
    int b = blockIdx.x, ty = blockIdx.y, tid = threadIdx.x;
    for (int i = tid; i < 16*16*9; i += 144) ws[i] = w2[i];
    int r0 = 6*ty - 1;
    for (int i = tid; i < 16*8*24; i += 144){
        int ci = i/(8*24), rr = (i/24)%8, cc = i%24;
        int gy = r0 + rr; float v = 0.f;
        if (gy >= 0 && gy < 24)
            v = fmaxf(g_h1[((size_t)b*16+ci)*576 + gy*24 + cc]*g_sc1[ci] + g_sh1[ci], 0.f);
        in_s[ci][rr][cc] = v;
    }
    __syncthreads();
    int ly = tid/24, lx = tid%24, gy = 6*ty + ly;
    float acc[16];
#pragma unroll
    for (int o = 0; o < 16; o++) acc[o] = b2[o];
    for (int ci = 0; ci < 16; ci++){
#pragma unroll
        for (int ky = 0; ky < 3; ky++){
#pragma unroll
            for (int kx = 0; kx < 3; kx++){
                int gx = lx + kx - 1;
                if (gx >= 0 && gx < 24){
                    float xv = in_s[ci][ly+ky][gx];
#pragma unroll
                    for (int o = 0; o < 16; o++) acc[o] += xv * ws[(o*16+ci)*9 + ky*3 + kx];
                }
            }
        }
    }
#pragma unroll
    for (int o = 0; o < 16; o++) g_h2[((size_t)b*16+o)*576 + gy*24 + lx] = acc[o];
}

// ---------- conv3: bn2+relu on load, 5x5 SAME ----------
__global__ __launch_bounds__(144) void k_conv3(const float* __restrict__ w3,
                                               const float* __restrict__ b3){
    __shared__ float in_s[16][10][24];
    __shared__ float ws[8*16*25];
    int b = blockIdx.x, ty = blockIdx.y, tid = threadIdx.x;
    for (int i = tid; i < 8*16*25; i += 144) ws[i] = w3[i];
    int r0 = 6*ty - 2;
    for (int i = tid; i < 16*10*24; i += 144){
        int ci = i/(10*24), rr = (i/24)%10, cc = i%24;
        int gy = r0 + rr; float v = 0.f;
        if (gy >= 0 && gy < 24)
            v = fmaxf(g_h2[((size_t)b*16+ci)*576 + gy*24 + cc]*g_sc2[ci] + g_sh2[ci], 0.f);
        in_s[ci][rr][cc] = v;
    }
    __syncthreads();
    int ly = tid/24, lx = tid%24, gy = 6*ty + ly;
    float acc[8];
#pragma unroll
    for (int o = 0; o < 8; o++) acc[o] = b3[o];
    for (int ci = 0; ci < 16; ci++){
#pragma unroll
        for (int ky = 0; ky < 5; ky++){
#pragma unroll
            for (int kx = 0; kx < 5; kx++){
                int gx = lx + kx - 2;
                if (gx >= 0 && gx < 24){
                    float xv = in_s[ci][ly+ky][gx];
#pragma unroll
                    for (int o = 0; o < 8; o++) acc[o] += xv * ws[(o*16+ci)*25 + ky*5 + kx];
                }
            }
        }
    }
#pragma unroll
    for (int o = 0; o < 8; o++) g_h3[((size_t)b*8+o)*576 + gy*24 + lx] = acc[o];
}

// ---------- tiny agent linears: op/om/mm ----------
__global__ void k_ag(const float* __restrict__ p, const float* __restrict__ m,
                     const float* __restrict__ phys_w, const float* __restrict__ phys_b,
                     const float* __restrict__ ment_w, const float* __restrict__ ment_b){
    int i = threadIdx.x;
    if (i < 192){
        int j = i/16, t = i%16;
        float s1 = phys_b[t], s2 = ment_b[t], s3 = ment_b[t];
        for (int k = 0; k < 16; k++){
            s1 += p[j*16+k] * phys_w[t*16+k];
            float mv = m[j*16+k];
            s2 += mv * ment_w[t*16+k];
            s3 += 0.9f * mv * ment_w[t*16+k];
        }
        g_op[i] = fmaxf(s1, 0.f);
        g_om[i] = fmaxf(s2, 0.f);
        g_mm[i] = fmaxf(s3, 0.f);
    }
}

// ---------- assemble lstm_in into agent-pair planes ----------
// layout: [0,4608) h3 | [4608,4624) phys-ag | [4624,4640) ment-ag |
//         [4640,4832) phys_inp (192) | [4832,5024) ment_inp (192)
__global__ void k_asm(const float* __restrict__ vis){
    int idx = blockIdx.x*256 + threadIdx.x;
    if (idx >= KA*INP) return;
    int b = idx / INP, col = idx % INP;
    float v;
    if (col < 4608){
        int ch = col/576, px = col%576;
        v = fmaxf(g_h3[((size_t)b*8+ch)*576 + px]*g_sc3[ch] + g_sh3[ch], 0.f);
    } else if (col < 4624) v = g_op[b*16 + col - 4608];
    else if (col < 4640)   v = g_om[b*16 + col - 4624];
    else if (col < 4832){ int r = col - 4640; v = vis[b*12 + r/16] * g_op[r]; }
    else                  v = g_mm[col - 4832];
    g_lsp[((size_t)(b>>1)*INP + col)*2 + (b&1)] = v;
}

// ---------- big weight-streaming GEMM: i,g,o gate rows only ----------
__global__ __launch_bounds__(128) void k_gemm(const float* __restrict__ w_ih){
    __shared__ ull ls[6][629];   // odd stride -> conflict-free LDS.64
    int rblk = blockIdx.x, chunk = blockIdx.y, tid = threadIdx.x;
    size_t c0 = (size_t)chunk * CSZ;
    const ull* gsrc = (const ull*)g_lsp;
    for (int i = tid; i < 6*629; i += 128){
        int pp = i/629, c = i%629;
        ((ull*)ls)[i] = (c < CSZ) ? gsrc[(size_t)pp*INP + c0 + c] : 0ULL;
    }
    __syncthreads();
    int warp = tid>>5, lane = tid&31;
    for (int pass = 0; pass < 8; pass++){
        int ridx = rblk*128 + pass*16 + warp*4;
        int gate = ridx / 4608, within = ridx - gate*4608;
        int gm = (gate==0) ? 0 : (gate==1 ? 2 : 3);   // i, g, o rows of w_ih
        const float* __restrict__ wr = w_ih + (size_t)(gm*4608 + within)*INP + c0;
        ull acc[4][6];
#pragma unroll
        for (int r = 0; r < 4; r++)
#pragma unroll
            for (int pp = 0; pp < 6; pp++) acc[r][pp] = 0ULL;
        for (int c = lane; c < CSZ; c += 32){
            ull W0 = dup2(wr[c]);
            ull W1 = dup2(wr[INP + c]);
            ull W2 = dup2(wr[2*INP + c]);
            ull W3 = dup2(wr[3*INP + c]);
#pragma unroll
            for (int pp = 0; pp < 6; pp++){
                ull l = ls[pp][c];
                acc[0][pp] = fma2(W0, l, acc[0][pp]);
                acc[1][pp] = fma2(W1, l, acc[1][pp]);
                acc[2][pp] = fma2(W2, l, acc[2][pp]);
                acc[3][pp] = fma2(W3, l, acc[3][pp]);
            }
        }
#pragma unroll
        for (int r = 0; r < 4; r++)
#pragma unroll
            for (int pp = 0; pp < 6; pp++){
                ull v = acc[r][pp];
#pragma unroll
                for (int off = 16; off; off >>= 1)
                    v = add2(v, __shfl_xor_sync(0xffffffffu, v, off));
                acc[r][pp] = v;
            }
        if (lane < 12){
            int pp = lane>>1, hi = lane&1;
#pragma unroll
            for (int r = 0; r < 4; r++){
                float lo_, hi_;
                asm("mov.b64 {%0,%1}, %2;" : "=f"(lo_), "=f"(hi_) : "l"(acc[r][pp]));
                g_part[((size_t)chunk*13824 + ridx + r)*KA + lane] = hi ? hi_ : lo_;
            }
        }
    }
}

// ---------- sum partials + LSTM activations -> relu(h) planes ----------
__global__ void k_fin(const float* __restrict__ b_ih, const float* __restrict__ b_hh){
    int idx = blockIdx.x*256 + threadIdx.x;
    if (idx >= KA*HSZ) return;
    int b = idx % KA, h = idx / KA;
    float si = b_ih[h] + b_hh[h];
    float sg = b_ih[9216 + h] + b_hh[9216 + h];
    float so = b_ih[13824 + h] + b_hh[13824 + h];
    for (int ch = 0; ch < NCH; ch++){
        const float* pp = g_part + (size_t)ch*13824*KA;
        si += pp[(size_t)h*KA + b];
        sg += pp[(size_t)(4608 + h)*KA + b];
        so += pp[(size_t)(9216 + h)*KA + b];
    }
    float c  = (1.f/(1.f + __expf(-si))) * tanhf(sg);
    float hv = (1.f/(1.f + __expf(-so))) * tanhf(c);
    g_hp[((size_t)(b>>1)*HSZ + h)*2 + (b&1)] = fmaxf(hv, 0.f);
}

// ---------- head GEMM (ah rows 0..127, inf rows 128..319) ----------
__global__ __launch_bounds__(128) void k_hgemm(const float* __restrict__ ah_w,
                                               const float* __restrict__ inf_w){
    __shared__ ull ls[6][769];
    int rblk = blockIdx.x, chunk = blockIdx.y, tid = threadIdx.x;
    size_t c0 = (size_t)chunk * CSZ2;
    const ull* gsrc = (const ull*)g_hp;
    for (int i = tid; i < 6*769; i += 128){
        int pp = i/769, c = i%769;
        ((ull*)ls)[i] = (c < CSZ2) ? gsrc[(size_t)pp*HSZ + c0 + c] : 0ULL;
    }
    __syncthreads();
    int warp = tid>>5, lane = tid&31;
    int ridx = rblk*16 + warp*4;
    const float* __restrict__ wb = (ridx < 128) ? ah_w + (size_t)ridx*HSZ + c0
                                                : inf_w + (size_t)(ridx-128)*HSZ + c0;
    ull acc[4][6];
#pragma unroll
    for (int r = 0; r < 4; r++)
#pragma unroll
        for (int pp = 0; pp < 6; pp++) acc[r][pp] = 0ULL;
    for (int c = lane; c < CSZ2; c += 32){
        ull W0 = dup2(wb[c]);
        ull W1 = dup2(wb[HSZ + c]);
        ull W2 = dup2(wb[2*HSZ + c]);
        ull W3 = dup2(wb[3*HSZ + c]);
#pragma unroll
        for (int pp = 0; pp < 6; pp++){
            ull l = ls[pp][c];
            acc[0][pp] = fma2(W0, l, acc[0][pp]);
            acc[1][pp] = fma2(W1, l, acc[1][pp]);
            acc[2][pp] = fma2(W2, l, acc[2][pp]);
            acc[3][pp] = fma2(W3, l, acc[3][pp]);
        }
    }
#pragma unroll
    for (int r = 0; r < 4; r++)
#pragma unroll
        for (int pp = 0; pp < 6; pp++){
            ull v = acc[r][pp];
#pragma unroll
            for (int off = 16; off; off >>= 1)
                v = add2(v, __shfl_xor_sync(0xffffffffu, v, off));
            acc[r][pp] = v;
        }
    if (lane < 12){
        int pp = lane>>1, hi = lane&1;
#pragma unroll
        for (int r = 0; r < 4; r++){
            float lo_, hi_;
            asm("mov.b64 {%0,%1}, %2;" : "=f"(lo_), "=f"(hi_) : "l"(acc[r][pp]));
            g_part2[((size_t)chunk*HROWS + ridx + r)*KA + lane] = hi ? hi_ : lo_;
        }
    }
}

// ---------- head finalize: relu(ah) -> g_t ; inf -> out old_ment ----------
__global__ void k_hfin(const float* __restrict__ ah_b, const float* __restrict__ inf_b,
                       float* __restrict__ out){
    int idx = blockIdx.x*256 + threadIdx.x;
    if (idx >= HROWS*KA) return;
    int b = idx % KA, r = idx / KA;
    float s = (r < 128) ? ah_b[r] : inf_b[r-128];
    for (int ch = 0; ch < NCH2; ch++)
        s += g_part2[((size_t)ch*HROWS + r)*KA + b];
    if (r < 128) g_t[b*128 + r] = fmaxf(s, 0.f);
    else         out[192 + b*192 + (r-128)] = s;
}

// ---------- tiny action head ----------
__global__ void k_act(const float* __restrict__ act_w, const float* __restrict__ act_b,
                      float* __restrict__ out){
    int i = threadIdx.x;
    if (i >= 192) return;
    int b = i/16, a = i%16;
    float s = act_b[a];
    for (int q = 0; q < 128; q++) s += g_t[b*128 + q] * act_w[a*128 + q];
    out[b*16 + a] = s;
}

extern "C" void kernel_launch(void* const* d_in, const int* in_sizes, int n_in,
                              void* d_out, int out_size){
    const float* x       = (const float*)d_in[0];
    const float* p       = (const float*)d_in[1];
    const float* m       = (const float*)d_in[2];
    const float* vis     = (const float*)d_in[3];
    const float* conv1_w = (const float*)d_in[4];
    const float* conv1_b = (const float*)d_in[5];
    const float* bn1_g   = (const float*)d_in[6];
    const float* bn1_b   = (const float*)d_in[7];
    const float* conv2_w = (const float*)d_in[8];
    const float* conv2_b = (const float*)d_in[9];
    const float* bn2_g   = (const float*)d_in[10];
    const float* bn2_b   = (const float*)d_in[11];
    const float* conv3_w = (const float*)d_in[12];
    const float* conv3_b = (const float*)d_in[13];
    const float* bn3_g   = (const float*)d_in[14];
    const float* bn3_b   = (const float*)d_in[15];
    const float* phys_w  = (const float*)d_in[16];
    const float* phys_b  = (const float*)d_in[17];
    const float* ment_w  = (const float*)d_in[18];
    const float* ment_b  = (const float*)d_in[19];
    const float* w_ih    = (const float*)d_in[20];
    /* w_ih index 20; w_hh (21) is dead: h0 = 0 */
    const float* b_ih    = (const float*)d_in[22];
    const float* b_hh    = (const float*)d_in[23];
    const float* ah_w    = (const float*)d_in[24];
    const float* ah_b    = (const float*)d_in[25];
    const float* act_w   = (const float*)d_in[26];
    const float* act_b   = (const float*)d_in[27];
    const float* inf_w   = (const float*)d_in[28];
    const float* inf_b   = (const float*)d_in[29];
    float* out = (float*)d_out;

    k_conv1<<<dim3(12,6), 96>>>(x, conv1_w, conv1_b);
    k_stats<<<16, 256>>>(0, bn1_g, bn1_b);
    k_conv2<<<dim3(12,4), 144>>>(conv2_w, conv2_b);
    k_stats<<<16, 256>>>(1, bn2_g, bn2_b);
    k_conv3<<<dim3(12,4), 144>>>(conv3_w, conv3_b);
    k_stats<<<8, 256>>>(2, bn3_g, bn3_b);
    k_ag<<<1, 192>>>(p, m, phys_w, phys_b, ment_w, ment_b);
    k_asm<<<(KA*INP + 255)/256, 256>>>(vis);
    k_gemm<<<dim3(NRB, NCH), 128>>>(w_ih);
    k_fin<<<(KA*HSZ + 255)/256, 256>>>(b_ih, b_hh);
    k_hgemm<<<dim3(HROWS/16, NCH2), 128>>>(ah_w, inf_w);
    k_hfin<<<(HROWS*KA + 255)/256, 256>>>(ah_b, inf_b, out);
    k_act<<<1, 192>>>(act_w, act_b, out);
}

// round 5
// speedup vs baseline: 1.0523x; 1.0523x over previous
#include <cuda_runtime.h>
#include <math.h>
#include <stdint.h>

typedef unsigned long long ull;

#define KA 12
#define HSZ 4608
#define INP 5024
#define EPSB 1e-5f
#define NPX 6912.f

// big gemm tiling
#define CSZ 628
#define CPAD 640
#define LSTR 642
#define NCH 8
#define NRB 108
// head gemm tiling
#define CSZ2 768
#define LSTR2 770
#define NCH2 6
#define HROWS 320

// scratch
__device__ __align__(16) float g_h1[KA*16*576];
__device__ __align__(16) float g_h2[KA*16*576];
__device__ __align__(16) float g_h3[KA*8*576];
__device__ float g_p1[72*16*2];
__device__ float g_p2[36*16*2];
__device__ float g_p3[36*8*2];
__device__ float g_op[192], g_om[192], g_mm[192];
__device__ __align__(16) float g_lsp[6*INP*2];
__device__ __align__(16) float g_part[(size_t)NCH*13824*KA];
__device__ __align__(16) float g_hp[6*HSZ*2];
__device__ __align__(16) float g_part2[(size_t)NCH2*HROWS*KA];

__device__ __forceinline__ ull dup2(float a){ ull r; asm("mov.b64 %0,{%1,%1};":"=l"(r):"f"(a)); return r; }
__device__ __forceinline__ ull fma2(ull a, ull b, ull c){ ull d; asm("fma.rn.f32x2 %0,%1,%2,%3;":"=l"(d):"l"(a),"l"(b),"l"(c)); return d; }
__device__ __forceinline__ ull add2(ull a, ull b){ ull d; asm("add.rn.f32x2 %0,%1,%2;":"=l"(d):"l"(a),"l"(b)); return d; }

// ---------- conv1: 1x1 over (c,d), no bias (cancels in BN), + per-block stats ----------
__global__ __launch_bounds__(96) void k_conv1(const float* __restrict__ x,
                                              const float* __restrict__ w1){
    __shared__ float ws[4096];
    __shared__ float sred[3][16][2];
    int b = blockIdx.x, t6 = blockIdx.y, tid = threadIdx.x;
    for (int i = tid; i < 4096; i += 96) ws[i] = w1[i];
    __syncthreads();
    int px = t6*96 + tid;
    float acc[16];
#pragma unroll
    for (int o = 0; o < 16; o++) acc[o] = 0.f;
    const float* xb = x + (size_t)b*147456 + px;
#pragma unroll 16
    for (int cd = 0; cd < 256; cd++){
        float xv = xb[(size_t)cd*576];
#pragma unroll
        for (int o = 0; o < 16; o++) acc[o] += xv * ws[o*256+cd];
    }
#pragma unroll
    for (int o = 0; o < 16; o++) g_h1[((size_t)b*16+o)*576 + px] = acc[o];
#pragma unroll
    for (int o = 0; o < 16; o++){
        float s = acc[o], q = acc[o]*acc[o];
#pragma unroll
        for (int off = 16; off; off >>= 1){
            s += __shfl_xor_sync(0xffffffffu, s, off);
            q += __shfl_xor_sync(0xffffffffu, q, off);
        }
        if ((tid&31)==0){ sred[tid>>5][o][0] = s; sred[tid>>5][o][1] = q; }
    }
    __syncthreads();
    if (tid < 16){
        int blk = b*6 + t6;
        g_p1[blk*32 + tid*2+0] = sred[0][tid][0]+sred[1][tid][0]+sred[2][tid][0];
        g_p1[blk*32 + tid*2+1] = sred[0][tid][1]+sred[1][tid][1]+sred[2][tid][1];
    }
}

// ---------- conv2: bn1 scale from partials, relu, 3x3 SAME, + stats partials ----------
__global__ __launch_bounds__(192) void k_conv2(const float* __restrict__ w2,
                                               const float* __restrict__ g1,
                                               const float* __restrict__ bb1){
    __shared__ float in_s[16][10][24];
    __shared__ float ws[2304];
    __shared__ float sc[16], sh[16];
    __shared__ float sred[6][16][2];
    int b = blockIdx.x, ty = blockIdx.y, tid = threadIdx.x;
    if (tid < 16){
        float S = 0.f, Q = 0.f;
#pragma unroll
        for (int i = 0; i < 72; i++){ S += g_p1[i*32+tid*2]; Q += g_p1[i*32+tid*2+1]; }
        float mu = S/NPX, var = Q/NPX - mu*mu;
        float r = rsqrtf(var + EPSB) * g1[tid];
        sc[tid] = r; sh[tid] = bb1[tid] - mu*r;
    }
    for (int i = tid; i < 2304; i += 192) ws[i] = w2[i];
    __syncthreads();
    int r0 = 8*ty - 1;
    for (int i = tid; i < 16*10*24; i += 192){
        int ci = i/240, rr = (i/24)%10, cc = i%24;
        int gy = r0 + rr; float v = 0.f;
        if (gy >= 0 && gy < 24)
            v = fmaxf(g_h1[((size_t)b*16+ci)*576 + gy*24 + cc]*sc[ci] + sh[ci], 0.f);
        in_s[ci][rr][cc] = v;
    }
    __syncthreads();
    int ly = tid/24, lx = tid%24, gy = 8*ty + ly;
    float acc[16];
#pragma unroll
    for (int o = 0; o < 16; o++) acc[o] = 0.f;
    for (int ci = 0; ci < 16; ci++){
#pragma unroll
        for (int ky = 0; ky < 3; ky++){
#pragma unroll
            for (int kx = 0; kx < 3; kx++){
                int gx = lx + kx - 1;
                if (gx >= 0 && gx < 24){
                    float xv = in_s[ci][ly+ky][gx];
#pragma unroll
                    for (int o = 0; o < 16; o++) acc[o] += xv * ws[(o*16+ci)*9 + ky*3 + kx];
                }
            }
        }
    }
#pragma unroll
    for (int o = 0; o < 16; o++) g_h2[((size_t)b*16+o)*576 + gy*24 + lx] = acc[o];
#pragma unroll
    for (int o = 0; o < 16; o++){
        float s = acc[o], q = acc[o]*acc[o];
#pragma unroll
        for (int off = 16; off; off >>= 1){
            s += __shfl_xor_sync(0xffffffffu, s, off);
            q += __shfl_xor_sync(0xffffffffu, q, off);
        }
        if ((tid&31)==0){ sred[tid>>5][o][0] = s; sred[tid>>5][o][1] = q; }
    }
    __syncthreads();
    if (tid < 16){
        float S = 0.f, Q = 0.f;
#pragma unroll
        for (int w = 0; w < 6; w++){ S += sred[w][tid][0]; Q += sred[w][tid][1]; }
        int blk = b*3 + ty;
        g_p2[blk*32 + tid*2+0] = S;
        g_p2[blk*32 + tid*2+1] = Q;
    }
}

// ---------- conv3: bn2 scale from partials, relu, 5x5 SAME, + stats partials ----------
__global__ __launch_bounds__(192) void k_conv3(const float* __restrict__ w3,
                                               const float* __restrict__ g2,
                                               const float* __restrict__ bb2){
    __shared__ float in_s[16][12][24];
    __shared__ float ws[3200];
    __shared__ float sc[16], sh[16];
    __shared__ float sred[6][8][2];
    int b = blockIdx.x, ty = blockIdx.y, tid = threadIdx.x;
    if (tid < 16){
        float S = 0.f, Q = 0.f;
#pragma unroll
        for (int i = 0; i < 36; i++){ S += g_p2[i*32+tid*2]; Q += g_p2[i*32+tid*2+1]; }
        float mu = S/NPX, var = Q/NPX - mu*mu;
        float r = rsqrtf(var + EPSB) * g2[tid];
        sc[tid] = r; sh[tid] = bb2[tid] - mu*r;
    }
    for (int i = tid; i < 3200; i += 192) ws[i] = w3[i];
    __syncthreads();
    int r0 = 8*ty - 2;
    for (int i = tid; i < 16*12*24; i += 192){
        int ci = i/288, rr = (i/24)%12, cc = i%24;
        int gy = r0 + rr; float v = 0.f;
        if (gy >= 0 && gy < 24)
            v = fmaxf(g_h2[((size_t)b*16+ci)*576 + gy*24 + cc]*sc[ci] + sh[ci], 0.f);
        in_s[ci][rr][cc] = v;
    }
    __syncthreads();
    int ly = tid/24, lx = tid%24, gy = 8*ty + ly;
    float acc[8];
#pragma unroll
    for (int o = 0; o < 8; o++) acc[o] = 0.f;
    for (int ci = 0; ci < 16; ci++){
#pragma unroll
        for (int ky = 0; ky < 5; ky++){
#pragma unroll
            for (int kx = 0; kx < 5; kx++){
                int gx = lx + kx - 2;
                if (gx >= 0 && gx < 24){
                    float xv = in_s[ci][ly+ky][gx];
#pragma unroll
                    for (int o = 0; o < 8; o++) acc[o] += xv * ws[(o*16+ci)*25 + ky*5 + kx];
                }
            }
        }
    }
#pragma unroll
    for (int o = 0; o < 8; o++) g_h3[((size_t)b*8+o)*576 + gy*24 + lx] = acc[o];
#pragma unroll
    for (int o = 0; o < 8; o++){
        float s = acc[o], q = acc[o]*acc[o];
#pragma unroll
        for (int off = 16; off; off >>= 1){
            s += __shfl_xor_sync(0xffffffffu, s, off);
            q += __shfl_xor_sync(0xffffffffu, q, off);
        }
        if ((tid&31)==0){ sred[tid>>5][o][0] = s; sred[tid>>5][o][1] = q; }
    }
    __syncthreads();
    if (tid < 8){
        float S = 0.f, Q = 0.f;
#pragma unroll
        for (int w = 0; w < 6; w++){ S += sred[w][tid][0]; Q += sred[w][tid][1]; }
        int blk = b*3 + ty;
        g_p3[blk*16 + tid*2+0] = S;
        g_p3[blk*16 + tid*2+1] = Q;
    }
}

// ---------- tiny agent linears ----------
__global__ void k_ag(const float* __restrict__ p, const float* __restrict__ m,
                     const float* __restrict__ phys_w, const float* __restrict__ phys_b,
                     const float* __restrict__ ment_w, const float* __restrict__ ment_b){
    int i = threadIdx.x;
    if (i < 192){
        int j = i/16, t = i%16;
        float s1 = phys_b[t], s2 = ment_b[t], s3 = ment_b[t];
        for (int k = 0; k < 16; k++){
            s1 += p[j*16+k] * phys_w[t*16+k];
            float mv = m[j*16+k];
            s2 += mv * ment_w[t*16+k];
            s3 += 0.9f * mv * ment_w[t*16+k];
        }
        g_op[i] = fmaxf(s1, 0.f);
        g_om[i] = fmaxf(s2, 0.f);
        g_mm[i] = fmaxf(s3, 0.f);
    }
}

// ---------- assemble lstm_in (bn3 scale from partials) ----------
__global__ void k_asm(const float* __restrict__ vis,
                      const float* __restrict__ g3, const float* __restrict__ bb3){
    __shared__ float sc[8], sh[8];
    int tid = threadIdx.x;
    if (tid < 8){
        float S = 0.f, Q = 0.f;
#pragma unroll
        for (int i = 0; i < 36; i++){ S += g_p3[i*16+tid*2]; Q += g_p3[i*16+tid*2+1]; }
        float mu = S/NPX, var = Q/NPX - mu*mu;
        float r = rsqrtf(var + EPSB) * g3[tid];
        sc[tid] = r; sh[tid] = bb3[tid] - mu*r;
    }
    __syncthreads();
    int idx = blockIdx.x*256 + tid;
    if (idx >= KA*INP) return;
    int b = idx / INP, col = idx % INP;
    float v;
    if (col < 4608){
        int ch = col/576, px = col%576;
        v = fmaxf(g_h3[((size_t)b*8+ch)*576 + px]*sc[ch] + sh[ch], 0.f);
    } else if (col < 4624) v = g_op[b*16 + col - 4608];
    else if (col < 4640)   v = g_om[b*16 + col - 4624];
    else if (col < 4832){ int r = col - 4640; v = vis[b*12 + r/16] * g_op[r]; }
    else                  v = g_mm[col - 4832];
    g_lsp[((size_t)(b>>1)*INP + col)*2 + (b&1)] = v;
}

// ---------- big weight-streaming GEMM (i,g,o rows only), float2 weights ----------
__global__ __launch_bounds__(128, 5) void k_gemm(const float* __restrict__ w_ih){
    __shared__ __align__(16) ull ls[6*LSTR];
    int rblk = blockIdx.x, chunk = blockIdx.y, tid = threadIdx.x;
    int c0 = chunk * CSZ;
    const ull* gsrc = (const ull*)g_lsp;
    for (int i = tid; i < 6*CPAD; i += 128){
        int pp = i/CPAD, c = i - pp*CPAD;
        ls[pp*LSTR + c] = (c < CSZ) ? gsrc[(size_t)pp*INP + c0 + c] : 0ULL;
    }
    __syncthreads();
    int warp = tid>>5, lane = tid&31;
    int cb = 2*lane;
    for (int pass = 0; pass < 8; pass++){
        int ridx = rblk*128 + pass*16 + warp*4;
        int gate = ridx / 4608;
        int gm = (gate==0) ? 0 : (gate==1 ? 2 : 3);
        const float* __restrict__ wr = w_ih + (size_t)(gm*4608 + ridx - gate*4608)*INP + c0;
        ull acc[4][6];
#pragma unroll
        for (int r = 0; r < 4; r++)
#pragma unroll
            for (int pp = 0; pp < 6; pp++) acc[r][pp] = 0ULL;
#pragma unroll
        for (int i = 0; i < 10; i++){
            int c = i*64 + cb;
            float2 wv0, wv1, wv2, wv3;
            if (c < CSZ){
                wv0 = *(const float2*)(wr + c);
                wv1 = *(const float2*)(wr + INP + c);
                wv2 = *(const float2*)(wr + 2*INP + c);
                wv3 = *(const float2*)(wr + 3*INP + c);
            } else {
                wv0 = wv1 = wv2 = wv3 = make_float2(0.f, 0.f);
            }
            ull W[4][2];
            W[0][0]=dup2(wv0.x); W[0][1]=dup2(wv0.y);
            W[1][0]=dup2(wv1.x); W[1][1]=dup2(wv1.y);
            W[2][0]=dup2(wv2.x); W[2][1]=dup2(wv2.y);
            W[3][0]=dup2(wv3.x); W[3][1]=dup2(wv3.y);
#pragma unroll
            for (int pp = 0; pp < 6; pp++){
                ulonglong2 lv = *(const ulonglong2*)&ls[pp*LSTR + c];
#pragma unroll
                for (int r = 0; r < 4; r++){
                    acc[r][pp] = fma2(W[r][0], lv.x, acc[r][pp]);
                    acc[r][pp] = fma2(W[r][1], lv.y, acc[r][pp]);
                }
            }
        }
#pragma unroll
        for (int r = 0; r < 4; r++)
#pragma unroll
            for (int pp = 0; pp < 6; pp++){
                ull v = acc[r][pp];
#pragma unroll
                for (int off = 16; off; off >>= 1)
                    v = add2(v, __shfl_xor_sync(0xffffffffu, v, off));
                acc[r][pp] = v;
            }
        if (lane < 12){
            int pp = lane>>1, hi = lane&1;
#pragma unroll
            for (int r = 0; r < 4; r++){
                float lo_, hi_;
                asm("mov.b64 {%0,%1}, %2;" : "=f"(lo_), "=f"(hi_) : "l"(acc[r][pp]));
                g_part[((size_t)chunk*13824 + ridx + r)*KA + lane] = hi ? hi_ : lo_;
            }
        }
    }
}

// ---------- sum partials + LSTM activations ----------
__global__ void k_fin(const float* __restrict__ b_ih, const float* __restrict__ b_hh){
    int idx = blockIdx.x*256 + threadIdx.x;
    if (idx >= KA*HSZ) return;
    int b = idx % KA, h = idx / KA;
    float si = b_ih[h] + b_hh[h];
    float sg = b_ih[9216 + h] + b_hh[9216 + h];
    float so = b_ih[13824 + h] + b_hh[13824 + h];
#pragma unroll
    for (int ch = 0; ch < NCH; ch++){
        const float* pp = g_part + (size_t)ch*13824*KA;
        si += pp[(size_t)h*KA + b];
        sg += pp[(size_t)(4608 + h)*KA + b];
        so += pp[(size_t)(9216 + h)*KA + b];
    }
    float c  = (1.f/(1.f + __expf(-si))) * tanhf(sg);
    float hv = (1.f/(1.f + __expf(-so))) * tanhf(c);
    g_hp[((size_t)(b>>1)*HSZ + h)*2 + (b&1)] = fmaxf(hv, 0.f);
}

// ---------- head GEMM ----------
__global__ __launch_bounds__(128) void k_hgemm(const float* __restrict__ ah_w,
                                               const float* __restrict__ inf_w){
    __shared__ __align__(16) ull ls[6*LSTR2];
    int rblk = blockIdx.x, chunk = blockIdx.y, tid = threadIdx.x;
    int c0 = chunk * CSZ2;
    const ull* gsrc = (const ull*)g_hp;
    for (int i = tid; i < 6*CSZ2; i += 128){
        int pp = i/CSZ2, c = i - pp*CSZ2;
        ls[pp*LSTR2 + c] = gsrc[(size_t)pp*HSZ + c0 + c];
    }
    __syncthreads();
    int warp = tid>>5, lane = tid&31;
    int cb = 2*lane;
    int ridx = rblk*16 + warp*4;
    const float* __restrict__ wb = (ridx < 128) ? ah_w + (size_t)ridx*HSZ + c0
                                                : inf_w + (size_t)(ridx-128)*HSZ + c0;
    ull acc[4][6];
#pragma unroll
    for (int r = 0; r < 4; r++)
#pragma unroll
        for (int pp = 0; pp < 6; pp++) acc[r][pp] = 0ULL;
#pragma unroll
    for (int i = 0; i < 12; i++){
        int c = i*64 + cb;
        float2 wv0 = *(const float2*)(wb + c);
        float2 wv1 = *(const float2*)(wb + HSZ + c);
        float2 wv2 = *(const float2*)(wb + 2*HSZ + c);
        float2 wv3 = *(const float2*)(wb + 3*HSZ + c);
        ull W[4][2];
        W[0][0]=dup2(wv0.x); W[0][1]=dup2(wv0.y);
        W[1][0]=dup2(wv1.x); W[1][1]=dup2(wv1.y);
        W[2][0]=dup2(wv2.x); W[2][1]=dup2(wv2.y);
        W[3][0]=dup2(wv3.x); W[3][1]=dup2(wv3.y);
#pragma unroll
        for (int pp = 0; pp < 6; pp++){
            ulonglong2 lv = *(const ulonglong2*)&ls[pp*LSTR2 + c];
#pragma unroll
            for (int r = 0; r < 4; r++){
                acc[r][pp] = fma2(W[r][0], lv.x, acc[r][pp]);
                acc[r][pp] = fma2(W[r][1], lv.y, acc[r][pp]);
            }
        }
    }
#pragma unroll
    for (int r = 0; r < 4; r++)
#pragma unroll
        for (int pp = 0; pp < 6; pp++){
            ull v = acc[r][pp];
#pragma unroll
            for (int off = 16; off; off >>= 1)
                v = add2(v, __shfl_xor_sync(0xffffffffu, v, off));
            acc[r][pp] = v;
        }
    if (lane < 12){
        int pp = lane>>1, hi = lane&1;
#pragma unroll
        for (int r = 0; r < 4; r++){
            float lo_, hi_;
            asm("mov.b64 {%0,%1}, %2;" : "=f"(lo_), "=f"(hi_) : "l"(acc[r][pp]));
            g_part2[((size_t)chunk*HROWS + ridx + r)*KA + lane] = hi ? hi_ : lo_;
        }
    }
}

// ---------- head finalize + action head (single block) ----------
__global__ __launch_bounds__(512) void k_hfinact(const float* __restrict__ ah_b,
                                                 const float* __restrict__ inf_b,
                                                 const float* __restrict__ act_w,
                                                 const float* __restrict__ act_b,
                                                 float* __restrict__ out){
    __shared__ float t[12*128];
    int tid = threadIdx.x;
    for (int idx = tid; idx < HROWS*KA; idx += 512){
        int b = idx % KA, r = idx / KA;
        float s = (r < 128) ? ah_b[r] : inf_b[r-128];
#pragma unroll
        for (int ch = 0; ch < NCH2; ch++)
            s += g_part2[((size_t)ch*HROWS + r)*KA + b];
        if (r < 128) t[b*128 + r] = fmaxf(s, 0.f);
        else         out[192 + b*192 + (r-128)] = s;
    }
    __syncthreads();
    if (tid < 192){
        int b = tid/16, a = tid%16;
        float s = act_b[a];
        for (int q = 0; q < 128; q++) s += t[b*128+q] * act_w[a*128+q];
        out[b*16 + a] = s;
    }
}

extern "C" void kernel_launch(void* const* d_in, const int* in_sizes, int n_in,
                              void* d_out, int out_size){
    const float* x       = (const float*)d_in[0];
    const float* p       = (const float*)d_in[1];
    const float* m       = (const float*)d_in[2];
    const float* vis     = (const float*)d_in[3];
    const float* conv1_w = (const float*)d_in[4];
    const float* bn1_g   = (const float*)d_in[6];
    const float* bn1_b   = (const float*)d_in[7];
    const float* conv2_w = (const float*)d_in[8];
    const float* bn2_g   = (const float*)d_in[10];
    const float* bn2_b   = (const float*)d_in[11];
    const float* conv3_w = (const float*)d_in[12];
    const float* bn3_g   = (const float*)d_in[14];
    const float* bn3_b   = (const float*)d_in[15];
    const float* phys_w  = (const float*)d_in[16];
    const float* phys_b  = (const float*)d_in[17];
    const float* ment_w  = (const float*)d_in[18];
    const float* ment_b  = (const float*)d_in[19];
    const float* w_ih    = (const float*)d_in[20];
    const float* b_ih    = (const float*)d_in[22];
    const float* b_hh    = (const float*)d_in[23];
    const float* ah_w    = (const float*)d_in[24];
    const float* ah_b    = (const float*)d_in[25];
    const float* act_w   = (const float*)d_in[26];
    const float* act_b   = (const float*)d_in[27];
    const float* inf_w   = (const float*)d_in[28];
    const float* inf_b   = (const float*)d_in[29];
    float* out = (float*)d_out;

    k_conv1<<<dim3(12,6), 96>>>(x, conv1_w);                      // 0
    k_conv2<<<dim3(12,3), 192>>>(conv2_w, bn1_g, bn1_b);          // 1
    k_conv3<<<dim3(12,3), 192>>>(conv3_w, bn2_g, bn2_b);          // 2
    k_ag<<<1, 192>>>(p, m, phys_w, phys_b, ment_w, ment_b);       // 3
    k_asm<<<(KA*INP + 255)/256, 256>>>(vis, bn3_g, bn3_b);        // 4
    k_gemm<<<dim3(NRB, NCH), 128>>>(w_ih);                        // 5  <- ncu -s 5
    k_fin<<<(KA*HSZ + 255)/256, 256>>>(b_ih, b_hh);               // 6
    k_hgemm<<<dim3(HROWS/16, NCH2), 128>>>(ah_w, inf_w);          // 7
    k_hfinact<<<1, 512>>>(ah_b, inf_b, act_w, act_b, out);        // 8
}